// round 13
// baseline (speedup 1.0000x reference)
#include <cuda_runtime.h>
#include <cuda_bf16.h>

#define NMAX 100000
#define EMAX 1600000
#define SCAN_B 256

// Scratch (device globals; no allocation allowed).
__device__ float4 g_h1[NMAX * 16];    // N x 64  (x@W1) ; later decoder hidden
__device__ float4 g_h2[NMAX * 8];     // N x 32  (z1@W2 via fused GEMV)
__device__ int    g_cnt[NMAX];
__device__ float  g_dinv[NMAX];
__device__ int    g_src[EMAX];
__device__ int    g_dst[EMAX];
__device__ int    g_rowptr[NMAX + 1];
__device__ int    g_cursor[NMAX];
__device__ int2   g_csr[EMAX];        // (src, norm-bits), grouped by dst
__device__ int    g_bsum[512];
__device__ int    g_arrive[2];

// ---------------------------------------------------------------------------
// f32x2 packed-FMA helpers (Blackwell FFMA2).
__device__ __forceinline__ unsigned long long pack2(float x) {
    unsigned long long r;
    asm("mov.b64 %0, {%1, %1};" : "=l"(r) : "f"(x));
    return r;
}
__device__ __forceinline__ void fma2(unsigned long long& d, unsigned long long a,
                                     unsigned long long b) {
    asm("fma.rn.f32x2 %0, %1, %2, %0;" : "+l"(d) : "l"(a), "l"(b));
}
__device__ __forceinline__ float2 unpack2(unsigned long long v) {
    float2 r;
    asm("mov.b64 {%0, %1}, %2;" : "=f"(r.x), "=f"(r.y) : "l"(v));
    return r;
}

// ---------------------------------------------------------------------------
// Convert indices -> int32 (clamped), histogram in-degree. Dtype detected
// block-locally (int64 LE -> odd words zero).
__global__ void prep_idx_kernel(const int* __restrict__ ei_raw, int e, int n) {
    int tid = threadIdx.x;
    int v = 0;
    if (tid < 128) v = ei_raw[2 * tid + 1];
    int is64 = __syncthreads_and(v == 0);

    int i = blockIdx.x * blockDim.x + tid;
    if (i >= e) return;
    int s, d;
    if (is64) {
        const long long* p = (const long long*)ei_raw;
        s = (int)p[i];
        d = (int)p[e + i];
    } else {
        s = ei_raw[i];
        d = ei_raw[e + i];
    }
    s = min(max(s, 0), n - 1);
    d = min(max(d, 0), n - 1);
    g_src[i] = s;
    g_dst[i] = d;
    atomicAdd(&g_cnt[d], 1);
}

__device__ __forceinline__ void grid_spin_barrier(int* ctr, int nblk, int t) {
    if (t == 0) {
        __threadfence();
        atomicAdd(ctr, 1);
        while (*(volatile int*)ctr < nblk) { }
        __threadfence();
    }
    __syncthreads();
}

// Fused scan + scatter (391 co-resident blocks; spin barriers safe).
__global__ void scan_scatter_kernel(int n, int e, int nblk) {
    __shared__ int s[SCAN_B];
    int t = threadIdx.x;
    int bid = blockIdx.x;
    int gid = bid * SCAN_B + t;
    int c = (gid < n) ? g_cnt[gid] : 0;
    s[t] = c;
    __syncthreads();
    for (int off = 1; off < SCAN_B; off <<= 1) {
        int add = (t >= off) ? s[t - off] : 0;
        __syncthreads();
        s[t] += add;
        __syncthreads();
    }
    int incl = s[t];
    int total = s[SCAN_B - 1];
    if (t == 0) g_bsum[bid] = total;
    grid_spin_barrier(&g_arrive[0], nblk, t);

    int pre = 0;
    for (int i = t; i < bid; i += SCAN_B) pre += g_bsum[i];
    __syncthreads();
    s[t] = pre;
    __syncthreads();
    for (int off = SCAN_B / 2; off > 0; off >>= 1) {
        if (t < off) s[t] += s[t + off];
        __syncthreads();
    }
    int ex = s[0] + incl - c;
    if (gid < n) {
        g_rowptr[gid] = ex;
        g_cursor[gid] = ex;
        g_dinv[gid]   = rsqrtf((float)c + 1.0f);
        if (gid == n - 1) g_rowptr[n] = ex + c;
    }
    grid_spin_barrier(&g_arrive[1], nblk, t);

    int stride = nblk * SCAN_B;
    for (int i = bid * SCAN_B + t; i < e; i += stride) {
        int ss = g_src[i], d = g_dst[i];
        int pos = atomicAdd(&g_cursor[d], 1);
        float nrm = g_dinv[ss] * g_dinv[d];
        g_csr[pos] = make_int2(ss, __float_as_int(nrm));
    }
}

// ---------------------------------------------------------------------------
// Layer 1 fused: warp-per-node pull over h1 (64-dim, float4/lane, 2 edges per
// round via half-warps), relu epilogue, then smem-based GEMV (64x32) -> h2.
// GEMV: z1 staged in smem, W2 transposed in smem; no SHFL.
#define W2T_S 68   // W2t row stride (floats): 68*4=272B, 16B aligned, conflict-free
__global__ void layer1_kernel(const float4* __restrict__ h4, float* __restrict__ h2out,
                              const float4* __restrict__ b1_4,
                              const float* __restrict__ W2, int n) {
    __shared__ float W2t[32 * W2T_S];        // [col][k] transposed
    __shared__ float4 z1s[8 * 16];           // per-warp z1 (64 floats = 16 float4)
    int tid = threadIdx.x;
    for (int i = tid; i < 64 * 32; i += 256) {
        int k = i >> 5, c = i & 31;
        W2t[c * W2T_S + k] = W2[i];
    }
    __syncthreads();

    int wid = tid >> 5;
    int lane = tid & 31;
    int gw = (blockIdx.x * blockDim.x + tid) >> 5;
    if (gw >= n) return;
    int half = lane >> 4;
    int hl   = lane & 15;
    int beg = g_rowptr[gw];
    int end = g_rowptr[gw + 1];

    float4 acc = make_float4(0.f, 0.f, 0.f, 0.f);
    int j = beg + half;
    for (; j + 6 < end; j += 8) {
        int2 m[4];
        float4 v[4];
#pragma unroll
        for (int q = 0; q < 4; q++) m[q] = g_csr[j + 2 * q];
#pragma unroll
        for (int q = 0; q < 4; q++) v[q] = h4[(size_t)m[q].x * 16 + hl];
#pragma unroll
        for (int q = 0; q < 4; q++) {
            float nm = __int_as_float(m[q].y);
            acc.x = fmaf(v[q].x, nm, acc.x);
            acc.y = fmaf(v[q].y, nm, acc.y);
            acc.z = fmaf(v[q].z, nm, acc.z);
            acc.w = fmaf(v[q].w, nm, acc.w);
        }
    }
    for (; j < end; j += 2) {
        int2 m = g_csr[j];
        float4 v = h4[(size_t)m.x * 16 + hl];
        float nm = __int_as_float(m.y);
        acc.x = fmaf(v.x, nm, acc.x);
        acc.y = fmaf(v.y, nm, acc.y);
        acc.z = fmaf(v.z, nm, acc.z);
        acc.w = fmaf(v.w, nm, acc.w);
    }
    acc.x += __shfl_xor_sync(0xffffffffu, acc.x, 16);
    acc.y += __shfl_xor_sync(0xffffffffu, acc.y, 16);
    acc.z += __shfl_xor_sync(0xffffffffu, acc.z, 16);
    acc.w += __shfl_xor_sync(0xffffffffu, acc.w, 16);

    float di = g_dinv[gw];
    float sl = di * di;
    float4 hv = h4[(size_t)gw * 16 + hl];
    float4 b = b1_4[hl];
    acc.x = fmaxf(fmaf(hv.x, sl, acc.x) + b.x, 0.f);
    acc.y = fmaxf(fmaf(hv.y, sl, acc.y) + b.y, 0.f);
    acc.z = fmaxf(fmaf(hv.z, sl, acc.z) + b.z, 0.f);
    acc.w = fmaxf(fmaf(hv.w, sl, acc.w) + b.w, 0.f);

    // Stage z1 (64 floats) to smem from lanes 0..15, then smem GEMV.
    if (lane < 16) z1s[wid * 16 + lane] = acc;
    __syncwarp();

    float hacc = 0.f;
#pragma unroll
    for (int k4 = 0; k4 < 16; k4++) {
        float4 zv = z1s[wid * 16 + k4];                              // broadcast
        float4 wv = *reinterpret_cast<const float4*>(&W2t[lane * W2T_S + k4 * 4]);
        hacc = fmaf(zv.x, wv.x, hacc);
        hacc = fmaf(zv.y, wv.y, hacc);
        hacc = fmaf(zv.z, wv.z, hacc);
        hacc = fmaf(zv.w, wv.w, hacc);
    }
    h2out[(size_t)gw * 32 + lane] = hacc;
}

// ---------------------------------------------------------------------------
// Layer 2 + decoder hidden fused: pull over h2 (32-dim, float4/lane, 4 edges
// per round), z -> z_out, then smem GEMV (32x64, Wd1 transposed) + bd1 + relu.
#define WD1T_S 36  // Wd1t row stride (floats): 144B, 16B aligned (2-way conflict)
__global__ void layer2_kernel(const float4* __restrict__ h4, float4* __restrict__ z_out4,
                              const float4* __restrict__ b2_4,
                              const float* __restrict__ Wd1,
                              const float* __restrict__ bd1,
                              float2* __restrict__ hidden, int n) {
    __shared__ float Wd1t[64 * WD1T_S];      // [col][k] transposed
    __shared__ float4 z2s[8 * 8];            // per-warp z (32 floats = 8 float4)
    __shared__ float bd1s[64];
    int tid = threadIdx.x;
    for (int i = tid; i < 32 * 64; i += 256) {
        int k = i >> 6, c = i & 63;
        Wd1t[c * WD1T_S + k] = Wd1[i];
    }
    if (tid < 16)
        reinterpret_cast<float4*>(bd1s)[tid] = reinterpret_cast<const float4*>(bd1)[tid];
    __syncthreads();

    int wid = tid >> 5;
    int lane = tid & 31;
    int gw = (blockIdx.x * blockDim.x + tid) >> 5;
    if (gw >= n) return;
    int q  = lane >> 3;
    int ql = lane & 7;
    int beg = g_rowptr[gw];
    int end = g_rowptr[gw + 1];

    float4 acc = make_float4(0.f, 0.f, 0.f, 0.f);
    int j = beg + q;
    for (; j + 12 < end; j += 16) {
        int2 m[4];
        float4 v[4];
#pragma unroll
        for (int p = 0; p < 4; p++) m[p] = g_csr[j + 4 * p];
#pragma unroll
        for (int p = 0; p < 4; p++) v[p] = h4[(size_t)m[p].x * 8 + ql];
#pragma unroll
        for (int p = 0; p < 4; p++) {
            float nm = __int_as_float(m[p].y);
            acc.x = fmaf(v[p].x, nm, acc.x);
            acc.y = fmaf(v[p].y, nm, acc.y);
            acc.z = fmaf(v[p].z, nm, acc.z);
            acc.w = fmaf(v[p].w, nm, acc.w);
        }
    }
    for (; j < end; j += 4) {
        int2 m = g_csr[j];
        float4 v = h4[(size_t)m.x * 8 + ql];
        float nm = __int_as_float(m.y);
        acc.x = fmaf(v.x, nm, acc.x);
        acc.y = fmaf(v.y, nm, acc.y);
        acc.z = fmaf(v.z, nm, acc.z);
        acc.w = fmaf(v.w, nm, acc.w);
    }
    acc.x += __shfl_xor_sync(0xffffffffu, acc.x, 8);
    acc.y += __shfl_xor_sync(0xffffffffu, acc.y, 8);
    acc.z += __shfl_xor_sync(0xffffffffu, acc.z, 8);
    acc.w += __shfl_xor_sync(0xffffffffu, acc.w, 8);
    acc.x += __shfl_xor_sync(0xffffffffu, acc.x, 16);
    acc.y += __shfl_xor_sync(0xffffffffu, acc.y, 16);
    acc.z += __shfl_xor_sync(0xffffffffu, acc.z, 16);
    acc.w += __shfl_xor_sync(0xffffffffu, acc.w, 16);

    float di = g_dinv[gw];
    float sl = di * di;
    float4 hv = h4[(size_t)gw * 8 + ql];
    float4 b = b2_4[ql];
    acc.x = fmaf(hv.x, sl, acc.x) + b.x;
    acc.y = fmaf(hv.y, sl, acc.y) + b.y;
    acc.z = fmaf(hv.z, sl, acc.z) + b.z;
    acc.w = fmaf(hv.w, sl, acc.w) + b.w;

    if (lane < 8) {
        z_out4[(size_t)gw * 8 + lane] = acc;
        z2s[wid * 8 + lane] = acc;
    }
    __syncwarp();

    // GEMV: hidden cols (2lane, 2lane+1) from smem z + transposed Wd1.
    const float2* bd1s2 = reinterpret_cast<const float2*>(bd1s);
    float2 hacc = bd1s2[lane];
#pragma unroll
    for (int k4 = 0; k4 < 8; k4++) {
        float4 zv = z2s[wid * 8 + k4];                               // broadcast
        float4 wa = *reinterpret_cast<const float4*>(&Wd1t[(2 * lane) * WD1T_S + k4 * 4]);
        float4 wb = *reinterpret_cast<const float4*>(&Wd1t[(2 * lane + 1) * WD1T_S + k4 * 4]);
        hacc.x = fmaf(zv.x, wa.x, hacc.x); hacc.y = fmaf(zv.x, wb.x, hacc.y);
        hacc.x = fmaf(zv.y, wa.y, hacc.x); hacc.y = fmaf(zv.y, wb.y, hacc.y);
        hacc.x = fmaf(zv.z, wa.z, hacc.x); hacc.y = fmaf(zv.z, wb.z, hacc.y);
        hacc.x = fmaf(zv.w, wa.w, hacc.x); hacc.y = fmaf(zv.w, wb.w, hacc.y);
    }
    hacc.x = fmaxf(hacc.x, 0.f);
    hacc.y = fmaxf(hacc.y, 0.f);
    hidden[(size_t)gw * 32 + lane] = hacc;
}

// ---------------------------------------------------------------------------
// Register-blocked GEMM, f32x2 packed FMAs, KC=32 K-chunks.
template <int KI, int KO, int RPB, bool BIAS, bool RELU>
__global__ void __launch_bounds__(256)
gemm_kernel(const float* __restrict__ in, const float* __restrict__ W,
            const float* __restrict__ bias, float* __restrict__ out, int n) {
    constexpr int TPC = KO / 4;
    constexpr int RT  = 256 / TPC;
    constexpr int R   = RPB / RT;
    static_assert(R >= 1 && R <= 4, "bad tile");
    constexpr int KC  = (KI < 32) ? KI : 32;
    constexpr int XP  = KC + 4;

    __shared__ float ws[KC * KO];
    __shared__ float xs[RPB * XP];

    int tid = threadIdx.x;
    int row0 = blockIdx.x * RPB;
    int ctid = tid % TPC;
    int rtid = tid / TPC;
    int r0 = rtid * R;

    unsigned long long acc[R][2];
#pragma unroll
    for (int i = 0; i < R; i++) { acc[i][0] = 0ull; acc[i][1] = 0ull; }

    for (int kc0 = 0; kc0 < KI; kc0 += KC) {
        for (int i = tid; i < KC * KO / 4; i += 256)
            reinterpret_cast<float4*>(ws)[i] =
                reinterpret_cast<const float4*>(W + (size_t)kc0 * KO)[i];
        for (int i = tid; i < RPB * KC / 4; i += 256) {
            int row = i / (KC / 4);
            int c4 = i % (KC / 4);
            int g = row0 + row;
            float4 v = make_float4(0.f, 0.f, 0.f, 0.f);
            if (g < n)
                v = reinterpret_cast<const float4*>(in)[(size_t)g * (KI / 4) + kc0 / 4 + c4];
            *reinterpret_cast<float4*>(&xs[row * XP + c4 * 4]) = v;
        }
        __syncthreads();

#pragma unroll
        for (int k4 = 0; k4 < KC / 4; k4++) {
            float4 xv[R];
#pragma unroll
            for (int i = 0; i < R; i++)
                xv[i] = *reinterpret_cast<const float4*>(&xs[(r0 + i) * XP + k4 * 4]);
#pragma unroll
            for (int kk = 0; kk < 4; kk++) {
                ulonglong2 w = *reinterpret_cast<const ulonglong2*>(
                    &ws[(k4 * 4 + kk) * KO + ctid * 4]);
#pragma unroll
                for (int i = 0; i < R; i++) {
                    float xsc = reinterpret_cast<const float*>(&xv[i])[kk];
                    unsigned long long xx = pack2(xsc);
                    fma2(acc[i][0], xx, w.x);
                    fma2(acc[i][1], xx, w.y);
                }
            }
        }
        __syncthreads();
    }

    float4 bv = make_float4(0.f, 0.f, 0.f, 0.f);
    if (BIAS) bv = *reinterpret_cast<const float4*>(&bias[ctid * 4]);
#pragma unroll
    for (int i = 0; i < R; i++) {
        int g = row0 + r0 + i;
        if (g >= n) continue;
        float2 lo = unpack2(acc[i][0]);
        float2 hi = unpack2(acc[i][1]);
        float4 o = make_float4(lo.x + bv.x, lo.y + bv.y, hi.x + bv.z, hi.y + bv.w);
        if (RELU) {
            o.x = fmaxf(o.x, 0.f); o.y = fmaxf(o.y, 0.f);
            o.z = fmaxf(o.z, 0.f); o.w = fmaxf(o.w, 0.f);
        }
        *reinterpret_cast<float4*>(&out[(size_t)g * KO + ctid * 4]) = o;
    }
}

// ---------------------------------------------------------------------------
extern "C" void kernel_launch(void* const* d_in, const int* in_sizes, int n_in,
                              void* d_out, int out_size) {
    const float* x   = (const float*)d_in[0];
    const void*  ei  = d_in[1];
    const float* W1  = (const float*)d_in[2];
    const float* b1  = (const float*)d_in[3];
    const float* W2  = (const float*)d_in[4];
    const float* b2  = (const float*)d_in[5];
    const float* Wd1 = (const float*)d_in[6];
    const float* bd1 = (const float*)d_in[7];
    const float* Wd2 = (const float*)d_in[8];
    const float* bd2 = (const float*)d_in[9];

    int n = in_sizes[0] / 128;   // 100000
    int e = in_sizes[1] / 2;     // 1600000

    float* rec_out = (float*)d_out;                 // [N,128]
    float* z_out   = rec_out + (long long)n * 128;  // [N,32]

    void *p_h1, *p_h2, *p_cnt, *p_arr;
    cudaGetSymbolAddress(&p_h1, g_h1);
    cudaGetSymbolAddress(&p_h2, g_h2);
    cudaGetSymbolAddress(&p_cnt, g_cnt);
    cudaGetSymbolAddress(&p_arr, g_arrive);
    float* h1 = (float*)p_h1;
    float* h2 = (float*)p_h2;

    const int B = 256;
    int warp_blocks = (n * 32 + B - 1) / B;
    int nblk = (n + SCAN_B - 1) / SCAN_B;   // 391

    // Fork a side stream so gemm1 (independent of the CSR build) overlaps
    // prep_idx + scan_scatter. Event fork/join keeps it graph-capturable.
    // Handles are intentionally not destroyed (capture is still active when
    // this function returns); a few leaked handles per process are harmless.
    cudaStream_t s2;
    cudaStreamCreate(&s2);
    cudaEvent_t e_fork, e_join;
    cudaEventCreate(&e_fork);
    cudaEventCreate(&e_join);

    cudaMemsetAsync(p_cnt, 0, (size_t)n * sizeof(int));
    cudaMemsetAsync(p_arr, 0, 2 * sizeof(int));

    cudaEventRecord(e_fork, 0);
    cudaStreamWaitEvent(s2, e_fork, 0);
    gemm_kernel<128, 64, 64, false, false><<<(n + 63) / 64, B, 0, s2>>>(x, W1, nullptr, h1, n);
    cudaEventRecord(e_join, s2);

    prep_idx_kernel<<<(e + B - 1) / B, B>>>((const int*)ei, e, n);
    scan_scatter_kernel<<<nblk, SCAN_B>>>(n, e, nblk);

    cudaStreamWaitEvent(0, e_join, 0);

    layer1_kernel<<<warp_blocks, B>>>((const float4*)h1, h2,
                                      (const float4*)b1, W2, n);
    layer2_kernel<<<warp_blocks, B>>>((const float4*)h2, (float4*)z_out,
                                      (const float4*)b2, Wd1, bd1,
                                      (float2*)h1, n);
    gemm_kernel<64, 128, 32, true, false><<<(n + 31) / 32, B>>>(h1, Wd2, bd2, rec_out, n);
}

// round 15
// speedup vs baseline: 1.6408x; 1.6408x over previous
#include <cuda_runtime.h>
#include <cuda_bf16.h>

#define NMAX 100000
#define EMAX 1600000
#define SCAN_B 256
#define W2T_S 68    // padded row stride (floats) for W2t smem: conflict-free LDS.128
#define WD1T_S 36   // padded row stride (floats) for Wd1t smem: conflict-free LDS.128

// Scratch (device globals; no allocation allowed).
__device__ float4 g_h1[NMAX * 16];    // N x 64  (x@W1) ; later decoder hidden
__device__ float4 g_h2[NMAX * 8];     // N x 32  (z1@W2 via fused GEMV)
__device__ int    g_cnt[NMAX];
__device__ float  g_dinv[NMAX];
__device__ int    g_src[EMAX];
__device__ int    g_dst[EMAX];
__device__ int    g_rowptr[NMAX + 1];
__device__ int    g_cursor[NMAX];
__device__ int2   g_csr[EMAX];        // (src, norm-bits), grouped by dst
__device__ int    g_bsum[512];
__device__ int    g_arrive[2];
__device__ float  g_W2t[32 * 64];     // W2 transposed: [col][k]
__device__ float  g_Wd1t[64 * 32];    // Wd1 transposed: [col][k]

// ---------------------------------------------------------------------------
// f32x2 packed-FMA helpers (Blackwell FFMA2).
__device__ __forceinline__ unsigned long long pack2(float x) {
    unsigned long long r;
    asm("mov.b64 %0, {%1, %1};" : "=l"(r) : "f"(x));
    return r;
}
__device__ __forceinline__ void fma2(unsigned long long& d, unsigned long long a,
                                     unsigned long long b) {
    asm("fma.rn.f32x2 %0, %1, %2, %0;" : "+l"(d) : "l"(a), "l"(b));
}
__device__ __forceinline__ float2 unpack2(unsigned long long v) {
    float2 r;
    asm("mov.b64 {%0, %1}, %2;" : "=f"(r.x), "=f"(r.y) : "l"(v));
    return r;
}

// ---------------------------------------------------------------------------
// Convert indices -> int32 (clamped), histogram in-degree. Dtype detected
// block-locally (int64 LE -> odd words zero). Last block also transposes
// W2 and Wd1 into global scratch (one-time, ~4k elements).
__global__ void prep_idx_kernel(const int* __restrict__ ei_raw, int e, int n,
                                const float* __restrict__ W2,
                                const float* __restrict__ Wd1) {
    int tid = threadIdx.x;
    if (blockIdx.x == gridDim.x - 1) {
        for (int i = tid; i < 64 * 32; i += 256) {
            int k = i >> 5, c = i & 31;            // W2[k][c]
            g_W2t[c * 64 + k] = W2[i];
        }
        for (int i = tid; i < 32 * 64; i += 256) {
            int k = i >> 6, c = i & 63;            // Wd1[k][c]
            g_Wd1t[c * 32 + k] = Wd1[i];
        }
    }
    int v = 0;
    if (tid < 128) v = ei_raw[2 * tid + 1];
    int is64 = __syncthreads_and(v == 0);

    int i = blockIdx.x * blockDim.x + tid;
    if (i >= e) return;
    int s, d;
    if (is64) {
        const long long* p = (const long long*)ei_raw;
        s = (int)p[i];
        d = (int)p[e + i];
    } else {
        s = ei_raw[i];
        d = ei_raw[e + i];
    }
    s = min(max(s, 0), n - 1);
    d = min(max(d, 0), n - 1);
    g_src[i] = s;
    g_dst[i] = d;
    atomicAdd(&g_cnt[d], 1);
}

__device__ __forceinline__ void grid_spin_barrier(int* ctr, int nblk, int t) {
    if (t == 0) {
        __threadfence();
        atomicAdd(ctr, 1);
        while (*(volatile int*)ctr < nblk) { }
        __threadfence();
    }
    __syncthreads();
}

// Fused scan + scatter (391 co-resident blocks; spin barriers safe).
__global__ void scan_scatter_kernel(int n, int e, int nblk) {
    __shared__ int s[SCAN_B];
    int t = threadIdx.x;
    int bid = blockIdx.x;
    int gid = bid * SCAN_B + t;
    int c = (gid < n) ? g_cnt[gid] : 0;
    s[t] = c;
    __syncthreads();
    for (int off = 1; off < SCAN_B; off <<= 1) {
        int add = (t >= off) ? s[t - off] : 0;
        __syncthreads();
        s[t] += add;
        __syncthreads();
    }
    int incl = s[t];
    int total = s[SCAN_B - 1];
    if (t == 0) g_bsum[bid] = total;
    grid_spin_barrier(&g_arrive[0], nblk, t);

    int pre = 0;
    for (int i = t; i < bid; i += SCAN_B) pre += g_bsum[i];
    __syncthreads();
    s[t] = pre;
    __syncthreads();
    for (int off = SCAN_B / 2; off > 0; off >>= 1) {
        if (t < off) s[t] += s[t + off];
        __syncthreads();
    }
    int ex = s[0] + incl - c;
    if (gid < n) {
        g_rowptr[gid] = ex;
        g_cursor[gid] = ex;
        g_dinv[gid]   = rsqrtf((float)c + 1.0f);
        if (gid == n - 1) g_rowptr[n] = ex + c;
    }
    grid_spin_barrier(&g_arrive[1], nblk, t);

    int stride = nblk * SCAN_B;
    for (int i = bid * SCAN_B + t; i < e; i += stride) {
        int ss = g_src[i], d = g_dst[i];
        int pos = atomicAdd(&g_cursor[d], 1);
        float nrm = g_dinv[ss] * g_dinv[d];
        g_csr[pos] = make_int2(ss, __float_as_int(nrm));
    }
}

// ---------------------------------------------------------------------------
// Layer 1 fused: warp-per-node pull over h1 (64-dim, float4/lane, 2 edges per
// round via half-warps), relu epilogue, smem GEMV (64x32) -> h2.
// W2t pre-transposed in global; smem staging is vectorized; all LDS.128
// accesses conflict-free (stride 68: quarter-warp banks 4l+{0..3}).
__global__ void layer1_kernel(const float4* __restrict__ h4, float* __restrict__ h2out,
                              const float4* __restrict__ b1_4, int n) {
    __shared__ float W2t[32 * W2T_S];        // [col][k]
    __shared__ float4 z1s[8 * 16];           // per-warp z1 (64 floats)
    int tid = threadIdx.x;
    for (int i = tid; i < 512; i += 256) {   // 512 float4 = 2048 floats
        int c = i >> 4, k4 = i & 15;
        float4 v = reinterpret_cast<const float4*>(g_W2t)[i];  // c*64+4k4
        *reinterpret_cast<float4*>(&W2t[c * W2T_S + k4 * 4]) = v;
    }
    __syncthreads();

    int wid = tid >> 5;
    int lane = tid & 31;
    int gw = (blockIdx.x * blockDim.x + tid) >> 5;
    if (gw >= n) return;
    int half = lane >> 4;
    int hl   = lane & 15;
    int beg = g_rowptr[gw];
    int end = g_rowptr[gw + 1];

    float4 acc = make_float4(0.f, 0.f, 0.f, 0.f);
    int j = beg + half;
    for (; j + 6 < end; j += 8) {
        int2 m[4];
        float4 v[4];
#pragma unroll
        for (int q = 0; q < 4; q++) m[q] = g_csr[j + 2 * q];
#pragma unroll
        for (int q = 0; q < 4; q++) v[q] = h4[(size_t)m[q].x * 16 + hl];
#pragma unroll
        for (int q = 0; q < 4; q++) {
            float nm = __int_as_float(m[q].y);
            acc.x = fmaf(v[q].x, nm, acc.x);
            acc.y = fmaf(v[q].y, nm, acc.y);
            acc.z = fmaf(v[q].z, nm, acc.z);
            acc.w = fmaf(v[q].w, nm, acc.w);
        }
    }
    for (; j < end; j += 2) {
        int2 m = g_csr[j];
        float4 v = h4[(size_t)m.x * 16 + hl];
        float nm = __int_as_float(m.y);
        acc.x = fmaf(v.x, nm, acc.x);
        acc.y = fmaf(v.y, nm, acc.y);
        acc.z = fmaf(v.z, nm, acc.z);
        acc.w = fmaf(v.w, nm, acc.w);
    }
    acc.x += __shfl_xor_sync(0xffffffffu, acc.x, 16);
    acc.y += __shfl_xor_sync(0xffffffffu, acc.y, 16);
    acc.z += __shfl_xor_sync(0xffffffffu, acc.z, 16);
    acc.w += __shfl_xor_sync(0xffffffffu, acc.w, 16);

    float di = g_dinv[gw];
    float sl = di * di;
    float4 hv = h4[(size_t)gw * 16 + hl];
    float4 b = b1_4[hl];
    acc.x = fmaxf(fmaf(hv.x, sl, acc.x) + b.x, 0.f);
    acc.y = fmaxf(fmaf(hv.y, sl, acc.y) + b.y, 0.f);
    acc.z = fmaxf(fmaf(hv.z, sl, acc.z) + b.z, 0.f);
    acc.w = fmaxf(fmaf(hv.w, sl, acc.w) + b.w, 0.f);

    // Stage z1 to smem (lanes 0..15 hold cols 4hl..4hl+3), then vector GEMV.
    if (lane < 16) z1s[wid * 16 + lane] = acc;
    __syncwarp();

    float hacc = 0.f;
#pragma unroll
    for (int k4 = 0; k4 < 16; k4++) {
        float4 zv = z1s[wid * 16 + k4];                                   // broadcast
        float4 wv = *reinterpret_cast<const float4*>(&W2t[lane * W2T_S + k4 * 4]);
        hacc = fmaf(zv.x, wv.x, hacc);
        hacc = fmaf(zv.y, wv.y, hacc);
        hacc = fmaf(zv.z, wv.z, hacc);
        hacc = fmaf(zv.w, wv.w, hacc);
    }
    h2out[(size_t)gw * 32 + lane] = hacc;
}

// ---------------------------------------------------------------------------
// Layer 2 + decoder hidden fused: pull over h2 (32-dim, float4/lane, 4 edges
// per round), z -> z_out, smem GEMV (32x64) + bd1 + relu -> hidden.
// Lane computes hidden cols (lane, lane+32): both Wd1t reads conflict-free.
__global__ void layer2_kernel(const float4* __restrict__ h4, float4* __restrict__ z_out4,
                              const float4* __restrict__ b2_4,
                              const float* __restrict__ bd1,
                              float* __restrict__ hidden, int n) {
    __shared__ float Wd1t[64 * WD1T_S];      // [col][k]
    __shared__ float4 z2s[8 * 8];            // per-warp z (32 floats)
    int tid = threadIdx.x;
    for (int i = tid; i < 512; i += 256) {   // 512 float4 = 2048 floats
        int c = i >> 3, k4 = i & 7;
        float4 v = reinterpret_cast<const float4*>(g_Wd1t)[i]; // c*32+4k4
        *reinterpret_cast<float4*>(&Wd1t[c * WD1T_S + k4 * 4]) = v;
    }
    __syncthreads();

    int wid = tid >> 5;
    int lane = tid & 31;
    int gw = (blockIdx.x * blockDim.x + tid) >> 5;
    if (gw >= n) return;
    int q  = lane >> 3;
    int ql = lane & 7;
    int beg = g_rowptr[gw];
    int end = g_rowptr[gw + 1];

    float4 acc = make_float4(0.f, 0.f, 0.f, 0.f);
    int j = beg + q;
    for (; j + 12 < end; j += 16) {
        int2 m[4];
        float4 v[4];
#pragma unroll
        for (int p = 0; p < 4; p++) m[p] = g_csr[j + 4 * p];
#pragma unroll
        for (int p = 0; p < 4; p++) v[p] = h4[(size_t)m[p].x * 8 + ql];
#pragma unroll
        for (int p = 0; p < 4; p++) {
            float nm = __int_as_float(m[p].y);
            acc.x = fmaf(v[p].x, nm, acc.x);
            acc.y = fmaf(v[p].y, nm, acc.y);
            acc.z = fmaf(v[p].z, nm, acc.z);
            acc.w = fmaf(v[p].w, nm, acc.w);
        }
    }
    for (; j < end; j += 4) {
        int2 m = g_csr[j];
        float4 v = h4[(size_t)m.x * 8 + ql];
        float nm = __int_as_float(m.y);
        acc.x = fmaf(v.x, nm, acc.x);
        acc.y = fmaf(v.y, nm, acc.y);
        acc.z = fmaf(v.z, nm, acc.z);
        acc.w = fmaf(v.w, nm, acc.w);
    }
    acc.x += __shfl_xor_sync(0xffffffffu, acc.x, 8);
    acc.y += __shfl_xor_sync(0xffffffffu, acc.y, 8);
    acc.z += __shfl_xor_sync(0xffffffffu, acc.z, 8);
    acc.w += __shfl_xor_sync(0xffffffffu, acc.w, 8);
    acc.x += __shfl_xor_sync(0xffffffffu, acc.x, 16);
    acc.y += __shfl_xor_sync(0xffffffffu, acc.y, 16);
    acc.z += __shfl_xor_sync(0xffffffffu, acc.z, 16);
    acc.w += __shfl_xor_sync(0xffffffffu, acc.w, 16);

    float di = g_dinv[gw];
    float sl = di * di;
    float4 hv = h4[(size_t)gw * 8 + ql];
    float4 b = b2_4[ql];
    acc.x = fmaf(hv.x, sl, acc.x) + b.x;
    acc.y = fmaf(hv.y, sl, acc.y) + b.y;
    acc.z = fmaf(hv.z, sl, acc.z) + b.z;
    acc.w = fmaf(hv.w, sl, acc.w) + b.w;

    if (lane < 8) {
        z_out4[(size_t)gw * 8 + lane] = acc;
        z2s[wid * 8 + lane] = acc;
    }
    __syncwarp();

    // GEMV: lane computes hidden cols lane and lane+32.
    float ha = bd1[lane];
    float hb = bd1[lane + 32];
#pragma unroll
    for (int k4 = 0; k4 < 8; k4++) {
        float4 zv = z2s[wid * 8 + k4];                                    // broadcast
        float4 wa = *reinterpret_cast<const float4*>(&Wd1t[lane * WD1T_S + k4 * 4]);
        float4 wb = *reinterpret_cast<const float4*>(&Wd1t[(lane + 32) * WD1T_S + k4 * 4]);
        ha = fmaf(zv.x, wa.x, ha); hb = fmaf(zv.x, wb.x, hb);
        ha = fmaf(zv.y, wa.y, ha); hb = fmaf(zv.y, wb.y, hb);
        ha = fmaf(zv.z, wa.z, ha); hb = fmaf(zv.z, wb.z, hb);
        ha = fmaf(zv.w, wa.w, ha); hb = fmaf(zv.w, wb.w, hb);
    }
    hidden[(size_t)gw * 64 + lane]      = fmaxf(ha, 0.f);
    hidden[(size_t)gw * 64 + lane + 32] = fmaxf(hb, 0.f);
}

// ---------------------------------------------------------------------------
// Register-blocked GEMM, f32x2 packed FMAs, KC=32 K-chunks.
template <int KI, int KO, int RPB, bool BIAS, bool RELU>
__global__ void __launch_bounds__(256)
gemm_kernel(const float* __restrict__ in, const float* __restrict__ W,
            const float* __restrict__ bias, float* __restrict__ out, int n) {
    constexpr int TPC = KO / 4;
    constexpr int RT  = 256 / TPC;
    constexpr int R   = RPB / RT;
    static_assert(R >= 1 && R <= 4, "bad tile");
    constexpr int KC  = (KI < 32) ? KI : 32;
    constexpr int XP  = KC + 4;

    __shared__ float ws[KC * KO];
    __shared__ float xs[RPB * XP];

    int tid = threadIdx.x;
    int row0 = blockIdx.x * RPB;
    int ctid = tid % TPC;
    int rtid = tid / TPC;
    int r0 = rtid * R;

    unsigned long long acc[R][2];
#pragma unroll
    for (int i = 0; i < R; i++) { acc[i][0] = 0ull; acc[i][1] = 0ull; }

    for (int kc0 = 0; kc0 < KI; kc0 += KC) {
        for (int i = tid; i < KC * KO / 4; i += 256)
            reinterpret_cast<float4*>(ws)[i] =
                reinterpret_cast<const float4*>(W + (size_t)kc0 * KO)[i];
        for (int i = tid; i < RPB * KC / 4; i += 256) {
            int row = i / (KC / 4);
            int c4 = i % (KC / 4);
            int g = row0 + row;
            float4 v = make_float4(0.f, 0.f, 0.f, 0.f);
            if (g < n)
                v = reinterpret_cast<const float4*>(in)[(size_t)g * (KI / 4) + kc0 / 4 + c4];
            *reinterpret_cast<float4*>(&xs[row * XP + c4 * 4]) = v;
        }
        __syncthreads();

#pragma unroll
        for (int k4 = 0; k4 < KC / 4; k4++) {
            float4 xv[R];
#pragma unroll
            for (int i = 0; i < R; i++)
                xv[i] = *reinterpret_cast<const float4*>(&xs[(r0 + i) * XP + k4 * 4]);
#pragma unroll
            for (int kk = 0; kk < 4; kk++) {
                ulonglong2 w = *reinterpret_cast<const ulonglong2*>(
                    &ws[(k4 * 4 + kk) * KO + ctid * 4]);
#pragma unroll
                for (int i = 0; i < R; i++) {
                    float xsc = reinterpret_cast<const float*>(&xv[i])[kk];
                    unsigned long long xx = pack2(xsc);
                    fma2(acc[i][0], xx, w.x);
                    fma2(acc[i][1], xx, w.y);
                }
            }
        }
        __syncthreads();
    }

    float4 bv = make_float4(0.f, 0.f, 0.f, 0.f);
    if (BIAS) bv = *reinterpret_cast<const float4*>(&bias[ctid * 4]);
#pragma unroll
    for (int i = 0; i < R; i++) {
        int g = row0 + r0 + i;
        if (g >= n) continue;
        float2 lo = unpack2(acc[i][0]);
        float2 hi = unpack2(acc[i][1]);
        float4 o = make_float4(lo.x + bv.x, lo.y + bv.y, hi.x + bv.z, hi.y + bv.w);
        if (RELU) {
            o.x = fmaxf(o.x, 0.f); o.y = fmaxf(o.y, 0.f);
            o.z = fmaxf(o.z, 0.f); o.w = fmaxf(o.w, 0.f);
        }
        *reinterpret_cast<float4*>(&out[(size_t)g * KO + ctid * 4]) = o;
    }
}

// ---------------------------------------------------------------------------
extern "C" void kernel_launch(void* const* d_in, const int* in_sizes, int n_in,
                              void* d_out, int out_size) {
    const float* x   = (const float*)d_in[0];
    const void*  ei  = d_in[1];
    const float* W1  = (const float*)d_in[2];
    const float* b1  = (const float*)d_in[3];
    const float* W2  = (const float*)d_in[4];
    const float* b2  = (const float*)d_in[5];
    const float* Wd1 = (const float*)d_in[6];
    const float* bd1 = (const float*)d_in[7];
    const float* Wd2 = (const float*)d_in[8];
    const float* bd2 = (const float*)d_in[9];

    int n = in_sizes[0] / 128;   // 100000
    int e = in_sizes[1] / 2;     // 1600000

    float* rec_out = (float*)d_out;                 // [N,128]
    float* z_out   = rec_out + (long long)n * 128;  // [N,32]

    void *p_h1, *p_h2, *p_cnt, *p_arr;
    cudaGetSymbolAddress(&p_h1, g_h1);
    cudaGetSymbolAddress(&p_h2, g_h2);
    cudaGetSymbolAddress(&p_cnt, g_cnt);
    cudaGetSymbolAddress(&p_arr, g_arrive);
    float* h1 = (float*)p_h1;
    float* h2 = (float*)p_h2;

    const int B = 256;
    int warp_blocks = (n * 32 + B - 1) / B;
    int nblk = (n + SCAN_B - 1) / SCAN_B;   // 391

    cudaMemsetAsync(p_cnt, 0, (size_t)n * sizeof(int));
    cudaMemsetAsync(p_arr, 0, 2 * sizeof(int));

    prep_idx_kernel<<<(e + B - 1) / B, B>>>((const int*)ei, e, n, W2, Wd1);   // k0
    scan_scatter_kernel<<<nblk, SCAN_B>>>(n, e, nblk);                        // k1
    gemm_kernel<128, 64, 64, false, false><<<(n + 63) / 64, B>>>(x, W1, nullptr, h1, n); // k2
    layer1_kernel<<<warp_blocks, B>>>((const float4*)h1, h2,
                                      (const float4*)b1, n);                  // k3 (profiled)
    layer2_kernel<<<warp_blocks, B>>>((const float4*)h2, (float4*)z_out,
                                      (const float4*)b2, bd1, h1, n);         // k4
    gemm_kernel<64, 128, 32, true, false><<<(n + 31) / 32, B>>>(h1, Wd2, bd2, rec_out, n); // k5
}

// round 17
// speedup vs baseline: 1.8068x; 1.1012x over previous
#include <cuda_runtime.h>
#include <cuda_bf16.h>

#define NMAX 100000
#define EMAX 1600000
#define SCAN_B 256

// Scratch (device globals; no allocation allowed).
__device__ float4 g_h1[NMAX * 16];    // N x 64  (x@W1) ; later decoder hidden
__device__ float4 g_h2[NMAX * 8];     // N x 32  (z1@W2 via fused block GEMM)
__device__ int    g_cnt[NMAX];
__device__ float  g_dinv[NMAX];
__device__ int    g_src[EMAX];
__device__ int    g_dst[EMAX];
__device__ int    g_rowptr[NMAX + 1];
__device__ int    g_cursor[NMAX];
__device__ int2   g_csr[EMAX];        // (src, norm-bits), grouped by dst
__device__ int    g_bsum[512];
__device__ int    g_arrive[2];

// ---------------------------------------------------------------------------
// f32x2 packed-FMA helpers (Blackwell FFMA2).
__device__ __forceinline__ unsigned long long pack2(float x) {
    unsigned long long r;
    asm("mov.b64 %0, {%1, %1};" : "=l"(r) : "f"(x));
    return r;
}
__device__ __forceinline__ void fma2(unsigned long long& d, unsigned long long a,
                                     unsigned long long b) {
    asm("fma.rn.f32x2 %0, %1, %2, %0;" : "+l"(d) : "l"(a), "l"(b));
}
__device__ __forceinline__ float2 unpack2(unsigned long long v) {
    float2 r;
    asm("mov.b64 {%0, %1}, %2;" : "=f"(r.x), "=f"(r.y) : "l"(v));
    return r;
}

// ---------------------------------------------------------------------------
// Convert indices -> int32 (clamped), histogram in-degree. Dtype detected
// block-locally (int64 LE -> odd words zero).
__global__ void prep_idx_kernel(const int* __restrict__ ei_raw, int e, int n) {
    int tid = threadIdx.x;
    int v = 0;
    if (tid < 128) v = ei_raw[2 * tid + 1];
    int is64 = __syncthreads_and(v == 0);

    int i = blockIdx.x * blockDim.x + tid;
    if (i >= e) return;
    int s, d;
    if (is64) {
        const long long* p = (const long long*)ei_raw;
        s = (int)p[i];
        d = (int)p[e + i];
    } else {
        s = ei_raw[i];
        d = ei_raw[e + i];
    }
    s = min(max(s, 0), n - 1);
    d = min(max(d, 0), n - 1);
    g_src[i] = s;
    g_dst[i] = d;
    atomicAdd(&g_cnt[d], 1);
}

__device__ __forceinline__ void grid_spin_barrier(int* ctr, int nblk, int t) {
    if (t == 0) {
        __threadfence();
        atomicAdd(ctr, 1);
        while (*(volatile int*)ctr < nblk) { }
        __threadfence();
    }
    __syncthreads();
}

// Fused scan + scatter (391 co-resident blocks; spin barriers safe).
__global__ void scan_scatter_kernel(int n, int e, int nblk) {
    __shared__ int s[SCAN_B];
    int t = threadIdx.x;
    int bid = blockIdx.x;
    int gid = bid * SCAN_B + t;
    int c = (gid < n) ? g_cnt[gid] : 0;
    s[t] = c;
    __syncthreads();
    for (int off = 1; off < SCAN_B; off <<= 1) {
        int add = (t >= off) ? s[t - off] : 0;
        __syncthreads();
        s[t] += add;
        __syncthreads();
    }
    int incl = s[t];
    int total = s[SCAN_B - 1];
    if (t == 0) g_bsum[bid] = total;
    grid_spin_barrier(&g_arrive[0], nblk, t);

    int pre = 0;
    for (int i = t; i < bid; i += SCAN_B) pre += g_bsum[i];
    __syncthreads();
    s[t] = pre;
    __syncthreads();
    for (int off = SCAN_B / 2; off > 0; off >>= 1) {
        if (t < off) s[t] += s[t + off];
        __syncthreads();
    }
    int ex = s[0] + incl - c;
    if (gid < n) {
        g_rowptr[gid] = ex;
        g_cursor[gid] = ex;
        g_dinv[gid]   = rsqrtf((float)c + 1.0f);
        if (gid == n - 1) g_rowptr[n] = ex + c;
    }
    grid_spin_barrier(&g_arrive[1], nblk, t);

    int stride = nblk * SCAN_B;
    for (int i = bid * SCAN_B + t; i < e; i += stride) {
        int ss = g_src[i], d = g_dst[i];
        int pos = atomicAdd(&g_cursor[d], 1);
        float nrm = g_dinv[ss] * g_dinv[d];
        g_csr[pos] = make_int2(ss, __float_as_int(nrm));
    }
}

// ---------------------------------------------------------------------------
// Layer 1 fused: phase 1 = warp-per-node pull over h1 (64-dim, float4/lane,
// 2 edges per round via half-warps) + relu epilogue -> z1s (smem).
// Phase 2 = warp 0 does the block's 8x64 @ 64x32 mini-GEMM with packed f32x2
// accumulators. h2 has only 32 cols, so: half-warp h handles rows 4h..4h+3,
// lane's col pair is 2*(lane&15) (in-bounds). W2 smem reads amortized over
// the block's 8 nodes.
__global__ void layer1_kernel(const float4* __restrict__ h4, float* __restrict__ h2out,
                              const float4* __restrict__ b1_4,
                              const float* __restrict__ W2, int n) {
    __shared__ float W2s[64 * 32];           // row-major copy of W2
    __shared__ float4 z1s[8 * 16];           // per-warp z1 (8 nodes x 64 floats)
    int tid = threadIdx.x;
    for (int i = tid; i < 512; i += 256)
        reinterpret_cast<float4*>(W2s)[i] = reinterpret_cast<const float4*>(W2)[i];

    int wid = tid >> 5;
    int lane = tid & 31;
    int node0 = blockIdx.x * 8;
    int gw = node0 + wid;

    if (gw < n) {
        int half = lane >> 4;
        int hl   = lane & 15;
        int beg = g_rowptr[gw];
        int end = g_rowptr[gw + 1];

        float4 acc = make_float4(0.f, 0.f, 0.f, 0.f);
        int j = beg + half;
        for (; j + 6 < end; j += 8) {
            int2 m[4];
            float4 v[4];
#pragma unroll
            for (int q = 0; q < 4; q++) m[q] = g_csr[j + 2 * q];
#pragma unroll
            for (int q = 0; q < 4; q++) v[q] = h4[(size_t)m[q].x * 16 + hl];
#pragma unroll
            for (int q = 0; q < 4; q++) {
                float nm = __int_as_float(m[q].y);
                acc.x = fmaf(v[q].x, nm, acc.x);
                acc.y = fmaf(v[q].y, nm, acc.y);
                acc.z = fmaf(v[q].z, nm, acc.z);
                acc.w = fmaf(v[q].w, nm, acc.w);
            }
        }
        for (; j < end; j += 2) {
            int2 m = g_csr[j];
            float4 v = h4[(size_t)m.x * 16 + hl];
            float nm = __int_as_float(m.y);
            acc.x = fmaf(v.x, nm, acc.x);
            acc.y = fmaf(v.y, nm, acc.y);
            acc.z = fmaf(v.z, nm, acc.z);
            acc.w = fmaf(v.w, nm, acc.w);
        }
        acc.x += __shfl_xor_sync(0xffffffffu, acc.x, 16);
        acc.y += __shfl_xor_sync(0xffffffffu, acc.y, 16);
        acc.z += __shfl_xor_sync(0xffffffffu, acc.z, 16);
        acc.w += __shfl_xor_sync(0xffffffffu, acc.w, 16);

        float di = g_dinv[gw];
        float sl = di * di;
        float4 hv = h4[(size_t)gw * 16 + hl];
        float4 b = b1_4[hl];
        acc.x = fmaxf(fmaf(hv.x, sl, acc.x) + b.x, 0.f);
        acc.y = fmaxf(fmaf(hv.y, sl, acc.y) + b.y, 0.f);
        acc.z = fmaxf(fmaf(hv.z, sl, acc.z) + b.z, 0.f);
        acc.w = fmaxf(fmaf(hv.w, sl, acc.w) + b.w, 0.f);

        if (lane < 16) z1s[wid * 16 + lane] = acc;   // cols 4l..4l+3 of row wid
    }
    __syncthreads();

    // Phase 2: warp 0. Half-warp h computes rows 4h..4h+3; col pair 2*(lane&15).
    if (wid == 0) {
        int half = lane >> 4;
        int c2   = 2 * (lane & 15);              // 0..30
        int r0   = 4 * half;
        unsigned long long acc2[4];
#pragma unroll
        for (int r = 0; r < 4; r++) acc2[r] = 0ull;
#pragma unroll
        for (int k4 = 0; k4 < 16; k4++) {
            unsigned long long wp[4];
#pragma unroll
            for (int kk = 0; kk < 4; kk++)
                wp[kk] = *reinterpret_cast<const unsigned long long*>(
                    &W2s[(4 * k4 + kk) * 32 + c2]);
#pragma unroll
            for (int r = 0; r < 4; r++) {
                float4 zr = z1s[(r0 + r) * 16 + k4];   // broadcast per half-warp
                fma2(acc2[r], pack2(zr.x), wp[0]);
                fma2(acc2[r], pack2(zr.y), wp[1]);
                fma2(acc2[r], pack2(zr.z), wp[2]);
                fma2(acc2[r], pack2(zr.w), wp[3]);
            }
        }
#pragma unroll
        for (int r = 0; r < 4; r++) {
            int row = node0 + r0 + r;
            if (row < n) {
                float2 o = unpack2(acc2[r]);
                *reinterpret_cast<float2*>(&h2out[(size_t)row * 32 + c2]) = o;
            }
        }
    }
}

// ---------------------------------------------------------------------------
// Layer 2 fused: phase 1 = warp-per-node pull over h2 (32-dim, float4/lane,
// 4 edges per round) + self + b2 -> z (z_out + z2s).
// Phase 2 = warp 0 does the block's 8x32 @ 32x64 mini-GEMM (Wd1, 64 cols:
// lane owns cols 2l,2l+1 exactly) + bd1 + relu -> decoder hidden.
__global__ void layer2_kernel(const float4* __restrict__ h4, float4* __restrict__ z_out4,
                              const float4* __restrict__ b2_4,
                              const float* __restrict__ Wd1,
                              const float* __restrict__ bd1,
                              float* __restrict__ hidden, int n) {
    __shared__ float Wd1s[32 * 64];          // row-major copy of Wd1
    __shared__ float4 z2s[8 * 8];            // per-warp z (8 nodes x 32 floats)
    int tid = threadIdx.x;
    for (int i = tid; i < 512; i += 256)
        reinterpret_cast<float4*>(Wd1s)[i] = reinterpret_cast<const float4*>(Wd1)[i];

    int wid = tid >> 5;
    int lane = tid & 31;
    int node0 = blockIdx.x * 8;
    int gw = node0 + wid;

    if (gw < n) {
        int q  = lane >> 3;
        int ql = lane & 7;
        int beg = g_rowptr[gw];
        int end = g_rowptr[gw + 1];

        float4 acc = make_float4(0.f, 0.f, 0.f, 0.f);
        int j = beg + q;
        for (; j + 12 < end; j += 16) {
            int2 m[4];
            float4 v[4];
#pragma unroll
            for (int p = 0; p < 4; p++) m[p] = g_csr[j + 4 * p];
#pragma unroll
            for (int p = 0; p < 4; p++) v[p] = h4[(size_t)m[p].x * 8 + ql];
#pragma unroll
            for (int p = 0; p < 4; p++) {
                float nm = __int_as_float(m[p].y);
                acc.x = fmaf(v[p].x, nm, acc.x);
                acc.y = fmaf(v[p].y, nm, acc.y);
                acc.z = fmaf(v[p].z, nm, acc.z);
                acc.w = fmaf(v[p].w, nm, acc.w);
            }
        }
        for (; j < end; j += 4) {
            int2 m = g_csr[j];
            float4 v = h4[(size_t)m.x * 8 + ql];
            float nm = __int_as_float(m.y);
            acc.x = fmaf(v.x, nm, acc.x);
            acc.y = fmaf(v.y, nm, acc.y);
            acc.z = fmaf(v.z, nm, acc.z);
            acc.w = fmaf(v.w, nm, acc.w);
        }
        acc.x += __shfl_xor_sync(0xffffffffu, acc.x, 8);
        acc.y += __shfl_xor_sync(0xffffffffu, acc.y, 8);
        acc.z += __shfl_xor_sync(0xffffffffu, acc.z, 8);
        acc.w += __shfl_xor_sync(0xffffffffu, acc.w, 8);
        acc.x += __shfl_xor_sync(0xffffffffu, acc.x, 16);
        acc.y += __shfl_xor_sync(0xffffffffu, acc.y, 16);
        acc.z += __shfl_xor_sync(0xffffffffu, acc.z, 16);
        acc.w += __shfl_xor_sync(0xffffffffu, acc.w, 16);

        float di = g_dinv[gw];
        float sl = di * di;
        float4 hv = h4[(size_t)gw * 8 + ql];
        float4 b = b2_4[ql];
        acc.x = fmaf(hv.x, sl, acc.x) + b.x;
        acc.y = fmaf(hv.y, sl, acc.y) + b.y;
        acc.z = fmaf(hv.z, sl, acc.z) + b.z;
        acc.w = fmaf(hv.w, sl, acc.w) + b.w;

        if (lane < 8) {
            z_out4[(size_t)gw * 8 + lane] = acc;
            z2s[wid * 8 + lane] = acc;
        }
    }
    __syncthreads();

    // Phase 2: warp 0 computes hidden rows node0..node0+7 (64 cols: exact fit).
    if (wid == 0) {
        int nodes = min(8, n - node0);
        unsigned long long bp = *reinterpret_cast<const unsigned long long*>(&bd1[2 * lane]);
        unsigned long long acc2[8];
#pragma unroll
        for (int r = 0; r < 8; r++) acc2[r] = bp;
#pragma unroll
        for (int k4 = 0; k4 < 8; k4++) {
            unsigned long long wp[4];
#pragma unroll
            for (int kk = 0; kk < 4; kk++)
                wp[kk] = *reinterpret_cast<const unsigned long long*>(
                    &Wd1s[(4 * k4 + kk) * 64 + 2 * lane]);
#pragma unroll
            for (int r = 0; r < 8; r++) {
                float4 zr = z2s[r * 8 + k4];         // broadcast
                fma2(acc2[r], pack2(zr.x), wp[0]);
                fma2(acc2[r], pack2(zr.y), wp[1]);
                fma2(acc2[r], pack2(zr.z), wp[2]);
                fma2(acc2[r], pack2(zr.w), wp[3]);
            }
        }
        for (int r = 0; r < nodes; r++) {
            float2 o = unpack2(acc2[r]);
            o.x = fmaxf(o.x, 0.f);
            o.y = fmaxf(o.y, 0.f);
            *reinterpret_cast<float2*>(&hidden[(size_t)(node0 + r) * 64 + 2 * lane]) = o;
        }
    }
}

// ---------------------------------------------------------------------------
// Register-blocked GEMM, f32x2 packed FMAs, KC=32 K-chunks.
template <int KI, int KO, int RPB, bool BIAS, bool RELU>
__global__ void __launch_bounds__(256)
gemm_kernel(const float* __restrict__ in, const float* __restrict__ W,
            const float* __restrict__ bias, float* __restrict__ out, int n) {
    constexpr int TPC = KO / 4;
    constexpr int RT  = 256 / TPC;
    constexpr int R   = RPB / RT;
    static_assert(R >= 1 && R <= 4, "bad tile");
    constexpr int KC  = (KI < 32) ? KI : 32;
    constexpr int XP  = KC + 4;

    __shared__ float ws[KC * KO];
    __shared__ float xs[RPB * XP];

    int tid = threadIdx.x;
    int row0 = blockIdx.x * RPB;
    int ctid = tid % TPC;
    int rtid = tid / TPC;
    int r0 = rtid * R;

    unsigned long long acc[R][2];
#pragma unroll
    for (int i = 0; i < R; i++) { acc[i][0] = 0ull; acc[i][1] = 0ull; }

    for (int kc0 = 0; kc0 < KI; kc0 += KC) {
        for (int i = tid; i < KC * KO / 4; i += 256)
            reinterpret_cast<float4*>(ws)[i] =
                reinterpret_cast<const float4*>(W + (size_t)kc0 * KO)[i];
        for (int i = tid; i < RPB * KC / 4; i += 256) {
            int row = i / (KC / 4);
            int c4 = i % (KC / 4);
            int g = row0 + row;
            float4 v = make_float4(0.f, 0.f, 0.f, 0.f);
            if (g < n)
                v = reinterpret_cast<const float4*>(in)[(size_t)g * (KI / 4) + kc0 / 4 + c4];
            *reinterpret_cast<float4*>(&xs[row * XP + c4 * 4]) = v;
        }
        __syncthreads();

#pragma unroll
        for (int k4 = 0; k4 < KC / 4; k4++) {
            float4 xv[R];
#pragma unroll
            for (int i = 0; i < R; i++)
                xv[i] = *reinterpret_cast<const float4*>(&xs[(r0 + i) * XP + k4 * 4]);
#pragma unroll
            for (int kk = 0; kk < 4; kk++) {
                ulonglong2 w = *reinterpret_cast<const ulonglong2*>(
                    &ws[(k4 * 4 + kk) * KO + ctid * 4]);
#pragma unroll
                for (int i = 0; i < R; i++) {
                    float xsc = reinterpret_cast<const float*>(&xv[i])[kk];
                    unsigned long long xx = pack2(xsc);
                    fma2(acc[i][0], xx, w.x);
                    fma2(acc[i][1], xx, w.y);
                }
            }
        }
        __syncthreads();
    }

    float4 bv = make_float4(0.f, 0.f, 0.f, 0.f);
    if (BIAS) bv = *reinterpret_cast<const float4*>(&bias[ctid * 4]);
#pragma unroll
    for (int i = 0; i < R; i++) {
        int g = row0 + r0 + i;
        if (g >= n) continue;
        float2 lo = unpack2(acc[i][0]);
        float2 hi = unpack2(acc[i][1]);
        float4 o = make_float4(lo.x + bv.x, lo.y + bv.y, hi.x + bv.z, hi.y + bv.w);
        if (RELU) {
            o.x = fmaxf(o.x, 0.f); o.y = fmaxf(o.y, 0.f);
            o.z = fmaxf(o.z, 0.f); o.w = fmaxf(o.w, 0.f);
        }
        *reinterpret_cast<float4*>(&out[(size_t)g * KO + ctid * 4]) = o;
    }
}

// ---------------------------------------------------------------------------
extern "C" void kernel_launch(void* const* d_in, const int* in_sizes, int n_in,
                              void* d_out, int out_size) {
    const float* x   = (const float*)d_in[0];
    const void*  ei  = d_in[1];
    const float* W1  = (const float*)d_in[2];
    const float* b1  = (const float*)d_in[3];
    const float* W2  = (const float*)d_in[4];
    const float* b2  = (const float*)d_in[5];
    const float* Wd1 = (const float*)d_in[6];
    const float* bd1 = (const float*)d_in[7];
    const float* Wd2 = (const float*)d_in[8];
    const float* bd2 = (const float*)d_in[9];

    int n = in_sizes[0] / 128;   // 100000
    int e = in_sizes[1] / 2;     // 1600000

    float* rec_out = (float*)d_out;                 // [N,128]
    float* z_out   = rec_out + (long long)n * 128;  // [N,32]

    void *p_h1, *p_h2, *p_cnt, *p_arr;
    cudaGetSymbolAddress(&p_h1, g_h1);
    cudaGetSymbolAddress(&p_h2, g_h2);
    cudaGetSymbolAddress(&p_cnt, g_cnt);
    cudaGetSymbolAddress(&p_arr, g_arrive);
    float* h1 = (float*)p_h1;
    float* h2 = (float*)p_h2;

    const int B = 256;
    int warp_blocks = (n * 32 + B - 1) / B;
    int nblk = (n + SCAN_B - 1) / SCAN_B;   // 391

    cudaMemsetAsync(p_cnt, 0, (size_t)n * sizeof(int));
    cudaMemsetAsync(p_arr, 0, 2 * sizeof(int));

    prep_idx_kernel<<<(e + B - 1) / B, B>>>((const int*)ei, e, n);            // k0
    scan_scatter_kernel<<<nblk, SCAN_B>>>(n, e, nblk);                        // k1
    gemm_kernel<128, 64, 64, false, false><<<(n + 63) / 64, B>>>(x, W1, nullptr, h1, n); // k2
    layer1_kernel<<<warp_blocks, B>>>((const float4*)h1, h2,
                                      (const float4*)b1, W2, n);              // k3 (profiled)
    layer2_kernel<<<warp_blocks, B>>>((const float4*)h2, (float4*)z_out,
                                      (const float4*)b2, Wd1, bd1, h1, n);    // k4
    gemm_kernel<64, 128, 32, true, false><<<(n + 31) / 32, B>>>(h1, Wd2, bd2, rec_out, n); // k5
}